// round 6
// baseline (speedup 1.0000x reference)
#include <cuda_runtime.h>
#include <math.h>

#define cB 8
#define cS 256
#define cH 768
#define cNH 4
#define cDH 192
#define cV 32000
#define cFF 3072
#define cSTEPS 32
#define cKV 1536
#define NBLK 148
#define NENG (2*NBLK)
#define ESMF 10240
#define PARTCAP (4*1024*1024)

// ---------------- static scratch ----------------
static __device__ float g_bias[cB*cS];
static __device__ float g_KV[3*cB*cS*cKV];        // per cross-attn module: rows [B*S], cols [K(768)|V(768)]
static __device__ float g_xctx[cB*cSTEPS*cH];
static __device__ float g_qkv0[cB*cSTEPS*3*cH];
static __device__ float g_dec[cB*cH];
static __device__ float g_qnew[cB*cH];
static __device__ float g_raw1[cB*cH];
static __device__ float g_h8[cB*cH];
static __device__ float g_x8[cB*cH];
static __device__ float g_ff8[cB*cFF];
static __device__ float g_x1[cB*cSTEPS*cH];
static __device__ float g_hb[cB*cSTEPS*cH];
static __device__ float g_qkv1[cB*cSTEPS*3*cH];
static __device__ float g_qb[cB*cSTEPS*cH];
static __device__ float g_rawb[cB*cSTEPS*cH];
static __device__ float g_ffb[cB*cSTEPS*cFF];
static __device__ float g_part[PARTCAP];
static __device__ volatile int g_bcnt;             // zero-init; always returns to 0
static __device__ volatile int g_bgen;             // monotonic generation

// ---------------- grid barrier (release/acquire via threadfence) ----------------
__device__ __forceinline__ void gbar()
{
    __syncthreads();
    if (threadIdx.x == 0) {
        int gen = g_bgen;
        __threadfence();                                   // release (CCTL.IVALL on sm_103a)
        if (atomicAdd((int*)&g_bcnt, 1) == (int)gridDim.x - 1) {
            g_bcnt = 0;
            __threadfence();
            g_bgen = gen + 1;
        } else {
            while (g_bgen == gen) __nanosleep(64);
        }
        __threadfence();                                   // acquire
    }
    __syncthreads();
}

__device__ __forceinline__ void esync(int ebar)
{
    asm volatile("bar.sync %0, 256;" :: "r"(ebar) : "memory");
}

// ---------------- phase: GEMM (engine = 256 thr, BM=64 BN=128 BK=16, 4x8) ----------------
__device__ void ph_gemm(const float* __restrict__ A, int lda,
                        const float* __restrict__ W,
                        const float* __restrict__ bias,
                        float* __restrict__ C, int ldc,
                        float* __restrict__ part,
                        int M, int N, int K, int S, int relu,
                        float* esm, int et, int geng, int ebar)
{
    float* As = esm;               // [16][68]
    float* Bs = esm + 16 * 68;     // [16][132]
    const int gx = N >> 7;
    const int gy = (M + 63) >> 6;
    const int nt = gx * gy * S;
    const int Kc = K / S;
    const int m0 = (et >> 4) * 4;
    const int n0 = (et & 15) * 8;
    const int arow = et >> 2, ac4 = et & 3;
    for (int tile = geng; tile < nt; tile += NENG) {
        int z = tile / (gx * gy);
        int rem = tile - z * (gx * gy);
        int by = rem / gx, bx = rem - by * gx;
        int bm = by << 6, bn = bx << 7;
        float acc[4][8] = {};
        int kbeg = z * Kc;
        for (int k0 = kbeg; k0 < kbeg + Kc; k0 += 16) {
            {
                int gm = bm + arow;
                float4 a = (gm < M) ? *(const float4*)(A + (size_t)gm * lda + k0 + ac4 * 4)
                                    : make_float4(0.f, 0.f, 0.f, 0.f);
                As[(ac4*4+0)*68 + arow] = a.x; As[(ac4*4+1)*68 + arow] = a.y;
                As[(ac4*4+2)*68 + arow] = a.z; As[(ac4*4+3)*68 + arow] = a.w;
            }
            #pragma unroll
            for (int i = 0; i < 2; i++) {
                int lin = i * 256 + et;
                int brow = lin >> 2, bc4 = lin & 3;
                float4 w = *(const float4*)(W + (size_t)(bn + brow) * K + k0 + bc4 * 4);
                Bs[(bc4*4+0)*132 + brow] = w.x; Bs[(bc4*4+1)*132 + brow] = w.y;
                Bs[(bc4*4+2)*132 + brow] = w.z; Bs[(bc4*4+3)*132 + brow] = w.w;
            }
            esync(ebar);
            #pragma unroll
            for (int kk = 0; kk < 16; kk++) {
                float4 av = *(const float4*)(As + kk*68 + m0);
                float4 b0 = *(const float4*)(Bs + kk*132 + n0);
                float4 b1 = *(const float4*)(Bs + kk*132 + n0 + 4);
                float a0[4] = {av.x,av.y,av.z,av.w};
                float bv[8] = {b0.x,b0.y,b0.z,b0.w,b1.x,b1.y,b1.z,b1.w};
                #pragma unroll
                for (int i = 0; i < 4; i++)
                    #pragma unroll
                    for (int j = 0; j < 8; j++)
                        acc[i][j] += a0[i] * bv[j];
            }
            esync(ebar);
        }
        if (S == 1) {
            #pragma unroll
            for (int i = 0; i < 4; i++) {
                int gm = bm + m0 + i;
                if (gm < M) {
                    float o[8];
                    #pragma unroll
                    for (int j = 0; j < 8; j++) {
                        float v = acc[i][j] + bias[bn + n0 + j];
                        o[j] = relu ? fmaxf(v, 0.f) : v;
                    }
                    float* cp = C + (size_t)gm * ldc + bn + n0;
                    *(float4*)(cp)     = make_float4(o[0],o[1],o[2],o[3]);
                    *(float4*)(cp + 4) = make_float4(o[4],o[5],o[6],o[7]);
                }
            }
        } else {
            float* P = part + (size_t)z * M * N;
            #pragma unroll
            for (int i = 0; i < 4; i++) {
                int gm = bm + m0 + i;
                if (gm < M) {
                    float* pp = P + (size_t)gm * N + bn + n0;
                    *(float4*)(pp)     = make_float4(acc[i][0],acc[i][1],acc[i][2],acc[i][3]);
                    *(float4*)(pp + 4) = make_float4(acc[i][4],acc[i][5],acc[i][6],acc[i][7]);
                }
            }
        }
    }
}

// ---------------- phase: split-K reduce (elementwise, fixed z order) ----------------
__device__ void ph_red(const float* __restrict__ part, const float* __restrict__ bias,
                       float* __restrict__ C, int ldc,
                       int M, int N, int S, int relu, int gtid, int gnt)
{
    int total = (M * N) >> 2;
    for (int e4 = gtid; e4 < total; e4 += gnt) {
        float4 s = *((const float4*)part + e4);
        for (int z = 1; z < S; z++) {
            float4 p = *((const float4*)part + (size_t)z * total + e4);
            s.x += p.x; s.y += p.y; s.z += p.z; s.w += p.w;
        }
        int n = (e4 << 2) % N, m = (e4 << 2) / N;
        float4 bb = *(const float4*)(bias + n);
        s.x += bb.x; s.y += bb.y; s.z += bb.z; s.w += bb.w;
        if (relu) {
            s.x = fmaxf(s.x, 0.f); s.y = fmaxf(s.y, 0.f);
            s.z = fmaxf(s.z, 0.f); s.w = fmaxf(s.w, 0.f);
        }
        *(float4*)(C + (size_t)m * ldc + n) = s;
    }
}

// ---------------- phase: GEMV for M=8 (warp = 4 cols; unit = 32 cols) ----------------
__device__ void ph_gemv(const float* __restrict__ X, int lda,
                        const float* __restrict__ W,
                        const float* __restrict__ bias,
                        float* __restrict__ C, int ldc,
                        int N, int K, int relu,
                        int et, int geng)
{
    const int lane = et & 31;
    const int w = et >> 5;
    const int nu = N >> 5;
    for (int u = geng; u < nu; u += NENG) {
        int n0 = u * 32 + w * 4;
        float acc[8][4] = {};
        for (int k = lane * 4; k < K; k += 128) {
            float4 w0 = __ldg((const float4*)(W + (size_t)(n0+0) * K + k));
            float4 w1 = __ldg((const float4*)(W + (size_t)(n0+1) * K + k));
            float4 w2 = __ldg((const float4*)(W + (size_t)(n0+2) * K + k));
            float4 w3 = __ldg((const float4*)(W + (size_t)(n0+3) * K + k));
            #pragma unroll
            for (int r = 0; r < 8; r++) {
                float4 xv = __ldg((const float4*)(X + (size_t)r * lda + k));
                acc[r][0] += xv.x*w0.x + xv.y*w0.y + xv.z*w0.z + xv.w*w0.w;
                acc[r][1] += xv.x*w1.x + xv.y*w1.y + xv.z*w1.z + xv.w*w1.w;
                acc[r][2] += xv.x*w2.x + xv.y*w2.y + xv.z*w2.z + xv.w*w2.w;
                acc[r][3] += xv.x*w3.x + xv.y*w3.y + xv.z*w3.z + xv.w*w3.w;
            }
        }
        #pragma unroll
        for (int r = 0; r < 8; r++) {
            #pragma unroll
            for (int j = 0; j < 4; j++) {
                float v = acc[r][j];
                #pragma unroll
                for (int o = 16; o; o >>= 1) v += __shfl_xor_sync(0xffffffffu, v, o);
                if (lane == 0) {
                    float y = v + bias[n0 + j];
                    C[(size_t)r * ldc + n0 + j] = relu ? fmaxf(y, 0.f) : y;
                }
            }
        }
    }
}

// ---------------- phase: cross attention (256 encoder keys, key bias) ----------------
__device__ void ph_xattn(const float* __restrict__ Q, int nq,
                         const float* __restrict__ KVb,   // K at +0, V at +cH, row stride cKV
                         const float* __restrict__ bias,
                         float* __restrict__ Out,
                         float* esm, int et, int geng, int ebar)
{
    float* qs = esm;                           // [8][193]
    float* ks = esm + 8*193;                   // [32][193]
    float* sc = esm + 8*193 + 32*193;          // [8][256]
    const float scale = 0.07216878364870322f;
    const int nbi = (nq + 7) >> 3;
    const int nu = 32 * nbi;
    for (int u = geng; u < nu; u += NENG) {
        int bh = u / nbi, ib = u - bh * nbi;
        int b = bh >> 2, h = bh & 3;
        int i0 = ib * 8;
        int ni = min(8, nq - i0);

        for (int idx = et; idx < ni * cDH; idx += 256) {
            int i = idx / cDH, d = idx - i * cDH;
            qs[i*193 + d] = Q[(size_t)(b * nq + i0 + i) * cH + h * cDH + d];
        }
        esync(ebar);

        for (int jt = 0; jt < cS; jt += 32) {
            for (int idx = et; idx < 32 * cDH; idx += 256) {
                int j = idx / cDH, d = idx - j * cDH;
                ks[j*193 + d] = KVb[(size_t)(b * cS + jt + j) * cKV + h * cDH + d];
            }
            esync(ebar);
            {
                int i = et >> 5, j = et & 31;
                if (i < ni) {
                    float s = 0.f;
                    #pragma unroll 8
                    for (int d = 0; d < cDH; d++) s += qs[i*193 + d] * ks[j*193 + d];
                    sc[i*256 + jt + j] = s * scale + bias[b * cS + jt + j];
                }
            }
            esync(ebar);
        }

        {
            int w = et >> 5, lane = et & 31;
            if (w < ni) {
                float mx = -3.4e38f;
                for (int j = lane; j < cS; j += 32) mx = fmaxf(mx, sc[w*256 + j]);
                #pragma unroll
                for (int o = 16; o; o >>= 1) mx = fmaxf(mx, __shfl_xor_sync(0xffffffffu, mx, o));
                float sum = 0.f;
                for (int j = lane; j < cS; j += 32) {
                    float e2 = expf(sc[w*256 + j] - mx);
                    sc[w*256 + j] = e2; sum += e2;
                }
                #pragma unroll
                for (int o = 16; o; o >>= 1) sum += __shfl_xor_sync(0xffffffffu, sum, o);
                float inv = 1.f / sum;
                for (int j = lane; j < cS; j += 32) sc[w*256 + j] *= inv;
            }
        }
        esync(ebar);

        {
            int i = et >> 5, lane = et & 31;
            float oacc[6] = {0.f,0.f,0.f,0.f,0.f,0.f};
            for (int jt = 0; jt < cS; jt += 32) {
                for (int idx = et; idx < 32 * cDH; idx += 256) {
                    int j = idx / cDH, d = idx - j * cDH;
                    ks[j*193 + d] = KVb[(size_t)(b * cS + jt + j) * cKV + cH + h * cDH + d];
                }
                esync(ebar);
                if (i < ni) {
                    float p = sc[i*256 + jt + lane];
                    #pragma unroll 8
                    for (int j = 0; j < 32; j++) {
                        float pj = __shfl_sync(0xffffffffu, p, j);
                        #pragma unroll
                        for (int k = 0; k < 6; k++)
                            oacc[k] += pj * ks[j*193 + lane + 32*k];
                    }
                }
                esync(ebar);
            }
            if (i < ni) {
                #pragma unroll
                for (int k = 0; k < 6; k++)
                    Out[(size_t)(b * nq + i0 + i) * cH + h * cDH + lane + 32*k] = oacc[k];
            }
        }
        esync(ebar);
    }
}

// ---------------- phase: self attention over decoder tokens (L<=32) ----------------
__device__ void ph_sattn(const float* __restrict__ QKV, int rs, int L,
                         float* __restrict__ Out, int lastonly,
                         float* esm, int et, int geng, int ebar)
{
    float* ks = esm;                 // [32][193]
    float* sc = esm + 32*193;        // [32][33]
    const float scale = 0.07216878364870322f;
    for (int u = geng; u < 32; u += NENG) {
        int b = u >> 2, h = u & 3;

        for (int idx = et; idx < L * cDH; idx += 256) {
            int j = idx / cDH, d = idx - j * cDH;
            ks[j*193 + d] = QKV[(size_t)(b * rs + j) * (3*cH) + cH + h * cDH + d];
        }
        esync(ebar);

        const int i_lo = lastonly ? (L - 1) : 0;
        const int nq2 = lastonly ? 1 : L;
        for (int idx = et; idx < nq2 * L; idx += 256) {
            int r = idx / L, j = idx - r * L;
            const float* q = QKV + (size_t)(b * rs + i_lo + r) * (3*cH) + h * cDH;
            float s = 0.f;
            #pragma unroll 8
            for (int d = 0; d < cDH; d++) s += q[d] * ks[j*193 + d];
            sc[r*33 + j] = s * scale;
        }
        esync(ebar);

        {
            int w = et >> 5, lane = et & 31;
            for (int r = w; r < nq2; r += 8) {
                float x = (lane < L) ? sc[r*33 + lane] : -3.4e38f;
                float mx = x;
                #pragma unroll
                for (int o = 16; o; o >>= 1) mx = fmaxf(mx, __shfl_xor_sync(0xffffffffu, mx, o));
                float e2 = (lane < L) ? expf(x - mx) : 0.f;
                float sum = e2;
                #pragma unroll
                for (int o = 16; o; o >>= 1) sum += __shfl_xor_sync(0xffffffffu, sum, o);
                if (lane < L) sc[r*33 + lane] = e2 / sum;
            }
        }
        esync(ebar);

        for (int idx = et; idx < L * cDH; idx += 256) {
            int j = idx / cDH, d = idx - j * cDH;
            ks[j*193 + d] = QKV[(size_t)(b * rs + j) * (3*cH) + 2*cH + h * cDH + d];
        }
        esync(ebar);

        if (lastonly) {
            if (et < cDH) {
                float acc = 0.f;
                for (int j = 0; j < L; j++) acc += sc[j] * ks[j*193 + et];
                Out[(size_t)b * cH + h * cDH + et] = acc;
            }
        } else {
            int w = et >> 5, lane = et & 31;
            for (int r = w; r < L; r += 8) {
                #pragma unroll
                for (int k = 0; k < 6; k++) {
                    int d = lane + 32*k;
                    float acc = 0.f;
                    for (int j = 0; j < L; j++) acc += sc[r*33 + j] * ks[j*193 + d];
                    Out[(size_t)(b * L + r) * cH + h * cDH + d] = acc;
                }
            }
        }
        esync(ebar);
    }
}

// ---------------- phase: residual + LayerNorm (engine per row) ----------------
__device__ void ph_addln(const float* __restrict__ X, int sx,
                         const float* __restrict__ Hh, int sh,
                         float* __restrict__ Y, int sy, int Lq,
                         const float* __restrict__ gamma,
                         const float* __restrict__ beta,
                         int Mrows, float* esm, int et, int geng, int ebar)
{
    float* red = esm;   // [8]
    for (int u = geng; u < Mrows; u += NENG) {
        int bb = u / Lq, l = u - bb * Lq;
        const float* x  = X  + ((size_t)bb * sx + l) * cH;
        const float* hh = Hh + ((size_t)bb * sh + l) * cH;
        float* y = Y + ((size_t)bb * sy + l) * cH;

        float v0 = x[et]       + hh[et];
        float v1 = x[et + 256] + hh[et + 256];
        float v2 = x[et + 512] + hh[et + 512];
        float s = v0 + v1 + v2;
        #pragma unroll
        for (int o = 16; o; o >>= 1) s += __shfl_xor_sync(0xffffffffu, s, o);
        if ((et & 31) == 0) red[et >> 5] = s;
        esync(ebar);
        float tot = 0.f;
        #pragma unroll
        for (int k = 0; k < 8; k++) tot += red[k];
        float mean = tot * (1.f / 768.f);
        float d0 = v0 - mean, d1 = v1 - mean, d2 = v2 - mean;
        float q = d0*d0 + d1*d1 + d2*d2;
        #pragma unroll
        for (int o = 16; o; o >>= 1) q += __shfl_xor_sync(0xffffffffu, q, o);
        esync(ebar);
        if ((et & 31) == 0) red[et >> 5] = q;
        esync(ebar);
        float vq = 0.f;
        #pragma unroll
        for (int k = 0; k < 8; k++) vq += red[k];
        float inv = rsqrtf(vq * (1.f / 768.f) + 1e-5f);
        y[et]       = d0 * inv * gamma[et]       + beta[et];
        y[et + 256] = d1 * inv * gamma[et + 256] + beta[et + 256];
        y[et + 512] = d2 * inv * gamma[et + 512] + beta[et + 512];
        esync(ebar);
    }
}

// ---------------- phase: argmax + token embed (engine per batch row) ----------------
__device__ void ph_argmax(const float* __restrict__ logits, int ldl,
                          const float* __restrict__ tok_w,
                          const float* __restrict__ tok_b,
                          float* __restrict__ dec,
                          float* esm, int et, int geng, int ebar)
{
    float* sv = esm;
    int* si = (int*)(esm + 256);
    for (int b = geng; b < cB; b += NENG) {
        const float* row = logits + (size_t)b * ldl;
        float best = -3.4e38f;
        int bidx = 0x7fffffff;
        for (int v = et; v < cV; v += 256) {
            float x = row[v];
            if (x > best || (x == best && v < bidx)) { best = x; bidx = v; }
        }
        sv[et] = best; si[et] = bidx;
        esync(ebar);
        for (int s = 128; s; s >>= 1) {
            if (et < s) {
                if (sv[et + s] > sv[et] || (sv[et + s] == sv[et] && si[et + s] < si[et])) {
                    sv[et] = sv[et + s]; si[et] = si[et + s];
                }
            }
            esync(ebar);
        }
        int id = si[0];
        for (int d = et; d < cH; d += 256)
            dec[b * cH + d] = tok_w[(size_t)d * cV + id] + tok_b[d];
        esync(ebar);
    }
}

// ---------------- small elementwise phases ----------------
__device__ void ph_bias(const int* __restrict__ mask, float* __restrict__ out, int gtid, int gnt)
{
    for (int i = gtid; i < cB * cS; i += gnt)
        out[i] = (mask[i] == 0) ? -1e9f : 0.f;
}

__device__ void ph_embed0(const int* __restrict__ sent, const float* __restrict__ temb,
                          float* __restrict__ dec, int gtid, int gnt)
{
    for (int i = gtid; i < cB * cH; i += gnt) {
        int b = i / cH, d = i - b * cH;
        dec[i] = temb[sent[b] * cH + d];
    }
}

__device__ __forceinline__ int pick_S(int gx, int gy, int M, int N)
{
    int g = gx * gy;
    int S = 1;
    while (S < 8 && g * S < NENG && (size_t)(S << 1) * M * N <= (size_t)PARTCAP) S <<= 1;
    return S;
}

// ---------------- the persistent kernel ----------------
__global__ __launch_bounds__(512, 1)
void persist_k(const float* __restrict__ hs, const int* __restrict__ sent,
               const int* __restrict__ amask, const float* __restrict__ temb,
               const float* ctx_in_w, const float* ctx_in_b,
               const float* ctx_out_w, const float* ctx_out_b,
               const float* self_in_w, const float* self_in_b,
               const float* self_out_w, const float* self_out_b,
               const float* cross_in_w, const float* cross_in_b,
               const float* cross_out_w, const float* cross_out_b,
               const float* ff1_w, const float* ff1_b,
               const float* ff2_w, const float* ff2_b,
               const float* norm_g, const float* norm_b,
               const float* out_w, const float* out_b,
               const float* tok_w, const float* tok_b,
               float* __restrict__ out)
{
    extern __shared__ float dsm[];
    const int tid = threadIdx.x;
    const int e = tid >> 8;
    const int et = tid & 255;
    const int ebar = 1 + e;
    float* esm = dsm + e * ESMF;
    const int geng = blockIdx.x * 2 + e;
    const int gtid = blockIdx.x * 512 + tid;
    const int gnt = (int)gridDim.x * 512;

#define DO_GEMM(A, lda, W, bias, C, ldc, M, N, K, relu) do { \
        int _gx = (N) >> 7, _gy = ((M) + 63) >> 6; \
        int _S = pick_S(_gx, _gy, (M), (N)); \
        ph_gemm((A), (lda), (W), (bias), (C), (ldc), g_part, (M), (N), (K), _S, (relu), esm, et, geng, ebar); \
        gbar(); \
        if (_S > 1) { ph_red(g_part, (bias), (C), (ldc), (M), (N), _S, (relu), gtid, gnt); gbar(); } \
    } while (0)

#define DO_BGEMM(A, lda, W, bias, C, ldc, M, N, K, relu) do { \
        if ((M) == 8) { ph_gemv((A), (lda), (W), (bias), (C), (ldc), (N), (K), (relu), et, geng); gbar(); } \
        else DO_GEMM(A, lda, W, bias, C, ldc, M, N, K, relu); \
    } while (0)

#define DO_GEMV(X, lda, W, bias, C, ldc, N, K, relu) do { \
        ph_gemv((X), (lda), (W), (bias), (C), (ldc), (N), (K), (relu), et, geng); gbar(); \
    } while (0)

    // ---- precompute ----
    ph_bias(amask, g_bias, gtid, gnt);
    gbar();
    for (int m = 0; m < 3; m++) {
        const float* w  = (m == 0) ? ctx_in_w : cross_in_w + (size_t)(m - 1) * 3 * cH * cH;
        const float* bb = (m == 0) ? ctx_in_b : cross_in_b + (size_t)(m - 1) * 3 * cH;
        DO_GEMM(hs, cH, w + (size_t)cH * cH, bb + cH,
                g_KV + (size_t)m * cB * cS * cKV, cKV, cB * cS, cKV, cH, 0);
    }

    // ---- generation loop ----
    for (int t = 0; t < cSTEPS; t++) {
        const int L = t + 1;
        const int M = cB * L;

        if (t == 0) ph_embed0(sent, temb, g_dec, gtid, gnt);
        else        ph_argmax(out + (size_t)(t - 1) * cV, cSTEPS * cV, tok_w, tok_b,
                              g_dec, esm, et, geng, ebar);
        gbar();

        // ctx attention for the new token -> cache slot t
        DO_GEMV(g_dec, cH, ctx_in_w, ctx_in_b, g_qnew, cH, cH, cH, 0);
        ph_xattn(g_qnew, 1, g_KV, g_bias, g_raw1, esm, et, geng, ebar);
        gbar();
        DO_GEMV(g_raw1, cH, ctx_out_w, ctx_out_b, g_xctx + (size_t)t * cH, cSTEPS * cH, cH, cH, 0);
        DO_GEMV(g_xctx + (size_t)t * cH, cSTEPS * cH, self_in_w, self_in_b,
                g_qkv0 + (size_t)t * 3 * cH, cSTEPS * 3 * cH, 3 * cH, cH, 0);

        // ---- layer 0 (all L positions) ----
        ph_sattn(g_qkv0, cSTEPS, L, g_rawb, 0, esm, et, geng, ebar);
        gbar();
        DO_BGEMM(g_rawb, cH, self_out_w, self_out_b, g_hb, cH, M, cH, cH, 0);
        ph_addln(g_xctx, cSTEPS, g_hb, L, g_x1, L, L, norm_g + 0 * cH, norm_b + 0 * cH,
                 M, esm, et, geng, ebar);
        gbar();
        DO_BGEMM(g_x1, cH, cross_in_w, cross_in_b, g_qb, cH, M, cH, cH, 0);
        ph_xattn(g_qb, L, g_KV + (size_t)1 * cB * cS * cKV, g_bias, g_rawb, esm, et, geng, ebar);
        gbar();
        DO_BGEMM(g_rawb, cH, cross_out_w, cross_out_b, g_hb, cH, M, cH, cH, 0);
        ph_addln(g_x1, L, g_hb, L, g_x1, L, L, norm_g + 1 * cH, norm_b + 1 * cH,
                 M, esm, et, geng, ebar);
        gbar();
        DO_BGEMM(g_x1, cH, ff1_w, ff1_b, g_ffb, cFF, M, cFF, cH, 1);
        DO_BGEMM(g_ffb, cFF, ff2_w, ff2_b, g_hb, cH, M, cH, cFF, 0);
        ph_addln(g_x1, L, g_hb, L, g_x1, L, L, norm_g + 2 * cH, norm_b + 2 * cH,
                 M, esm, et, geng, ebar);
        gbar();

        // ---- layer 1 (QKV for all L, rest last-position-only) ----
        DO_BGEMM(g_x1, cH, self_in_w + (size_t)3 * cH * cH, self_in_b + 3 * cH,
                 g_qkv1, 3 * cH, M, 3 * cH, cH, 0);
        ph_sattn(g_qkv1, L, L, g_raw1, 1, esm, et, geng, ebar);
        gbar();
        DO_GEMV(g_raw1, cH, self_out_w + (size_t)cH * cH, self_out_b + cH, g_h8, cH, cH, cH, 0);
        ph_addln(g_x1 + (size_t)(L - 1) * cH, L, g_h8, 1, g_x8, 1, 1,
                 norm_g + 3 * cH, norm_b + 3 * cH, cB, esm, et, geng, ebar);
        gbar();
        DO_GEMV(g_x8, cH, cross_in_w + (size_t)3 * cH * cH, cross_in_b + 3 * cH, g_qnew, cH, cH, cH, 0);
        ph_xattn(g_qnew, 1, g_KV + (size_t)2 * cB * cS * cKV, g_bias, g_raw1, esm, et, geng, ebar);
        gbar();
        DO_GEMV(g_raw1, cH, cross_out_w + (size_t)cH * cH, cross_out_b + cH, g_h8, cH, cH, cH, 0);
        ph_addln(g_x8, 1, g_h8, 1, g_x8, 1, 1, norm_g + 4 * cH, norm_b + 4 * cH,
                 cB, esm, et, geng, ebar);
        gbar();
        DO_GEMV(g_x8, cH, ff1_w + (size_t)cFF * cH, ff1_b + cFF, g_ff8, cFF, cFF, cH, 1);
        DO_GEMV(g_ff8, cFF, ff2_w + (size_t)cH * cFF, ff2_b + cH, g_h8, cH, cH, cFF, 0);
        ph_addln(g_x8, 1, g_h8, 1, g_x8, 1, 1, norm_g + 5 * cH, norm_b + 5 * cH,
                 cB, esm, et, geng, ebar);
        gbar();

        // ---- logits for this step ----
        DO_GEMV(g_x8, cH, out_w, out_b, out + (size_t)t * cV, cSTEPS * cV, cV, cH, 0);
    }
#undef DO_GEMM
#undef DO_BGEMM
#undef DO_GEMV
}

// ---------------- host ----------------
extern "C" void kernel_launch(void* const* d_in, const int* in_sizes, int n_in,
                              void* d_out, int out_size)
{
    (void)in_sizes; (void)n_in; (void)out_size;
    const float* hs          = (const float*)d_in[0];
    const int*   sent        = (const int*)d_in[1];
    const int*   amask       = (const int*)d_in[2];
    const float* temb        = (const float*)d_in[5];
    const float* ctx_in_w    = (const float*)d_in[6];
    const float* ctx_in_b    = (const float*)d_in[7];
    const float* ctx_out_w   = (const float*)d_in[8];
    const float* ctx_out_b   = (const float*)d_in[9];
    const float* self_in_w   = (const float*)d_in[10];
    const float* self_in_b   = (const float*)d_in[11];
    const float* self_out_w  = (const float*)d_in[12];
    const float* self_out_b  = (const float*)d_in[13];
    const float* cross_in_w  = (const float*)d_in[14];
    const float* cross_in_b  = (const float*)d_in[15];
    const float* cross_out_w = (const float*)d_in[16];
    const float* cross_out_b = (const float*)d_in[17];
    const float* ff1_w       = (const float*)d_in[18];
    const float* ff1_b       = (const float*)d_in[19];
    const float* ff2_w       = (const float*)d_in[20];
    const float* ff2_b       = (const float*)d_in[21];
    const float* norm_g      = (const float*)d_in[22];
    const float* norm_b      = (const float*)d_in[23];
    const float* out_w       = (const float*)d_in[24];
    const float* out_b       = (const float*)d_in[25];
    const float* tok_w       = (const float*)d_in[26];
    const float* tok_b       = (const float*)d_in[27];
    float* out = (float*)d_out;

    cudaFuncSetAttribute(persist_k, cudaFuncAttributeMaxDynamicSharedMemorySize,
                         2 * ESMF * (int)sizeof(float));
    persist_k<<<NBLK, 512, 2 * ESMF * sizeof(float)>>>(
        hs, sent, amask, temb,
        ctx_in_w, ctx_in_b, ctx_out_w, ctx_out_b,
        self_in_w, self_in_b, self_out_w, self_out_b,
        cross_in_w, cross_in_b, cross_out_w, cross_out_b,
        ff1_w, ff1_b, ff2_w, ff2_b, norm_g, norm_b,
        out_w, out_b, tok_w, tok_b, out);
}

// round 7
// speedup vs baseline: 1.1585x; 1.1585x over previous
#include <cuda_runtime.h>
#include <math.h>

#define cB 8
#define cS 256
#define cH 768
#define cNH 4
#define cDH 192
#define cV 32000
#define cFF 3072
#define cSTEPS 32
#define BSH (cB*cS*cH)
#define PARTCAP (8*1024*1024)

// ---------------- static scratch ----------------
static __device__ float g_bias[cB*cS];
static __device__ float g_Kc[3*BSH];
static __device__ float g_Vc[3*BSH];
static __device__ float g_xctx[cB*cSTEPS*cH];
static __device__ float g_qkv0[cB*cSTEPS*3*cH];
static __device__ float g_dec[cB*cH];
static __device__ float g_qnew[cB*cH];
static __device__ float g_raw1[cB*cH];
static __device__ float g_h8[cB*cH];
static __device__ float g_x8[cB*cH];
static __device__ float g_ff8[cB*cFF];
static __device__ float g_x1[cB*cSTEPS*cH];
static __device__ float g_hb[cB*cSTEPS*cH];
static __device__ float g_qkv1[cB*cSTEPS*3*cH];
static __device__ float g_qb[cB*cSTEPS*cH];
static __device__ float g_rawb[cB*cSTEPS*cH];
static __device__ float g_ffb[cB*cSTEPS*cFF];
static __device__ float g_part[PARTCAP];      // split-K partials (32 MB)
static __device__ int   g_cnt[256];           // per-tile tickets (zero-init; reset after use)

// ============ split-K GEMM v3: BM=64 BN=128 BK=16, 256 thr, 4x8, double-buffered ============
// C[M,N] = A[M,K] @ W[N,K]^T + bias (+relu). gridDim.z = S splits K.
__global__ __launch_bounds__(256)
void gemm_sk(const float* __restrict__ A, int lda,
             const float* __restrict__ W,
             const float* __restrict__ bias,
             float* __restrict__ C, int ldc,
             float* __restrict__ Cpart, int* __restrict__ cnt,
             int M, int N, int K, int relu)
{
    __shared__ float As[2][16][68];
    __shared__ float Bs[2][16][132];
    __shared__ int s_last;
    const int tid = threadIdx.x;
    const int bm = blockIdx.y * 64;
    const int bn = blockIdx.x * 128;
    const int S = gridDim.z;
    const int Kc = K / S;
    const int kbeg = blockIdx.z * Kc;
    const int ntile = Kc >> 4;
    const int m0 = (tid >> 4) * 4;
    const int n0 = (tid & 15) * 8;
    const int arow = tid >> 2, ac4 = tid & 3;
    const int brow0 = tid >> 2, brow1 = (256 + tid) >> 2;   // B rows for the 2 f4 loads
    float acc[4][8] = {};

    // ---- load tile 0 ----
    {
        int k0 = kbeg;
        int gm = bm + arow;
        float4 a = (gm < M) ? *(const float4*)(A + (size_t)gm * lda + k0 + ac4 * 4)
                            : make_float4(0.f, 0.f, 0.f, 0.f);
        As[0][ac4*4+0][arow] = a.x; As[0][ac4*4+1][arow] = a.y;
        As[0][ac4*4+2][arow] = a.z; As[0][ac4*4+3][arow] = a.w;
        float4 w0 = *(const float4*)(W + (size_t)(bn + brow0) * K + k0 + ac4 * 4);
        float4 w1 = *(const float4*)(W + (size_t)(bn + brow1) * K + k0 + ac4 * 4);
        Bs[0][ac4*4+0][brow0] = w0.x; Bs[0][ac4*4+1][brow0] = w0.y;
        Bs[0][ac4*4+2][brow0] = w0.z; Bs[0][ac4*4+3][brow0] = w0.w;
        Bs[0][ac4*4+0][brow1] = w1.x; Bs[0][ac4*4+1][brow1] = w1.y;
        Bs[0][ac4*4+2][brow1] = w1.z; Bs[0][ac4*4+3][brow1] = w1.w;
    }
    __syncthreads();

    for (int t = 0; t < ntile; t++) {
        const int cur = t & 1, nxt = cur ^ 1;
        const bool has = (t + 1) < ntile;
        float4 pa = make_float4(0.f,0.f,0.f,0.f), pw0, pw1;
        if (has) {
            int k0 = kbeg + (t + 1) * 16;
            int gm = bm + arow;
            if (gm < M) pa = *(const float4*)(A + (size_t)gm * lda + k0 + ac4 * 4);
            pw0 = *(const float4*)(W + (size_t)(bn + brow0) * K + k0 + ac4 * 4);
            pw1 = *(const float4*)(W + (size_t)(bn + brow1) * K + k0 + ac4 * 4);
        }
        #pragma unroll
        for (int kk = 0; kk < 16; kk++) {
            float4 av = *(const float4*)(&As[cur][kk][m0]);
            float4 b0 = *(const float4*)(&Bs[cur][kk][n0]);
            float4 b1 = *(const float4*)(&Bs[cur][kk][n0 + 4]);
            float a0[4] = {av.x,av.y,av.z,av.w};
            float bv[8] = {b0.x,b0.y,b0.z,b0.w,b1.x,b1.y,b1.z,b1.w};
            #pragma unroll
            for (int i = 0; i < 4; i++)
                #pragma unroll
                for (int j = 0; j < 8; j++)
                    acc[i][j] += a0[i] * bv[j];
        }
        if (has) {
            As[nxt][ac4*4+0][arow] = pa.x; As[nxt][ac4*4+1][arow] = pa.y;
            As[nxt][ac4*4+2][arow] = pa.z; As[nxt][ac4*4+3][arow] = pa.w;
            Bs[nxt][ac4*4+0][brow0] = pw0.x; Bs[nxt][ac4*4+1][brow0] = pw0.y;
            Bs[nxt][ac4*4+2][brow0] = pw0.z; Bs[nxt][ac4*4+3][brow0] = pw0.w;
            Bs[nxt][ac4*4+0][brow1] = pw1.x; Bs[nxt][ac4*4+1][brow1] = pw1.y;
            Bs[nxt][ac4*4+2][brow1] = pw1.z; Bs[nxt][ac4*4+3][brow1] = pw1.w;
        }
        __syncthreads();
    }

    if (S == 1) {
        #pragma unroll
        for (int i = 0; i < 4; i++) {
            int gm = bm + m0 + i;
            if (gm < M) {
                float o[8];
                #pragma unroll
                for (int j = 0; j < 8; j++) {
                    float v = acc[i][j] + bias[bn + n0 + j];
                    o[j] = relu ? fmaxf(v, 0.f) : v;
                }
                float* cp = C + (size_t)gm * ldc + bn + n0;
                *(float4*)(cp)     = make_float4(o[0],o[1],o[2],o[3]);
                *(float4*)(cp + 4) = make_float4(o[4],o[5],o[6],o[7]);
            }
        }
        return;
    }

    // write my partial (dense [z][M][N])
    {
        float* P = Cpart + (size_t)blockIdx.z * M * N;
        #pragma unroll
        for (int i = 0; i < 4; i++) {
            int gm = bm + m0 + i;
            if (gm < M) {
                float* pp = P + (size_t)gm * N + bn + n0;
                *(float4*)(pp)     = make_float4(acc[i][0],acc[i][1],acc[i][2],acc[i][3]);
                *(float4*)(pp + 4) = make_float4(acc[i][4],acc[i][5],acc[i][6],acc[i][7]);
            }
        }
    }
    __threadfence();
    __syncthreads();
    if (tid == 0) {
        int tix = blockIdx.y * gridDim.x + blockIdx.x;
        int old = atomicAdd(&cnt[tix], 1);
        s_last = (old == S - 1) ? 1 : 0;
        if (s_last) cnt[tix] = 0;
    }
    __syncthreads();
    if (!s_last) return;

    // last block: reduce tile (64x128 = 2048 f4; 8 f4/thread) in fixed z order
    #pragma unroll
    for (int e = 0; e < 8; e++) {
        int lin = e * 256 + tid;
        int r = lin >> 5;
        int c = (lin & 31) * 4;
        int gm = bm + r;
        if (gm >= M) continue;
        const float* P0 = Cpart + (size_t)gm * N + bn + c;
        float4 s = *(const float4*)(P0);
        for (int z = 1; z < S; z++) {
            float4 p = *(const float4*)(P0 + (size_t)z * M * N);
            s.x += p.x; s.y += p.y; s.z += p.z; s.w += p.w;
        }
        float4 bb = *(const float4*)(bias + bn + c);
        s.x += bb.x; s.y += bb.y; s.z += bb.z; s.w += bb.w;
        if (relu) {
            s.x = fmaxf(s.x, 0.f); s.y = fmaxf(s.y, 0.f);
            s.z = fmaxf(s.z, 0.f); s.w = fmaxf(s.w, 0.f);
        }
        *(float4*)(C + (size_t)gm * ldc + bn + c) = s;
    }
}

// ============ GEMV (M=8): warp computes 4 output columns, coalesced W ============
__global__ __launch_bounds__(256)
void gemv_w4(const float* __restrict__ X, int lda,
             const float* __restrict__ W,
             const float* __restrict__ bias,
             float* __restrict__ C, int ldc,
             int N, int K, int relu)
{
    __shared__ float xs[8][768];
    const int tid = threadIdx.x;
    const int lane = tid & 31;
    const int wid = tid >> 5;
    const int n0 = (blockIdx.x * 8 + wid) * 4;
    float acc[8][4] = {};

    for (int kt = 0; kt < K; kt += 768) {
        #pragma unroll
        for (int i = 0; i < 6; i++) {
            int lin = i * 256 + tid;
            int row = lin / 192, c4 = lin % 192;
            *(float4*)(&xs[row][c4 * 4]) =
                *(const float4*)(X + (size_t)row * lda + kt + c4 * 4);
        }
        __syncthreads();
        #pragma unroll
        for (int i = 0; i < 6; i++) {
            int k = i * 128 + lane * 4;
            float4 w0 = *(const float4*)(W + (size_t)(n0+0) * K + kt + k);
            float4 w1 = *(const float4*)(W + (size_t)(n0+1) * K + kt + k);
            float4 w2 = *(const float4*)(W + (size_t)(n0+2) * K + kt + k);
            float4 w3 = *(const float4*)(W + (size_t)(n0+3) * K + kt + k);
            #pragma unroll
            for (int r = 0; r < 8; r++) {
                float4 xv = *(const float4*)(&xs[r][k]);
                acc[r][0] += xv.x*w0.x + xv.y*w0.y + xv.z*w0.z + xv.w*w0.w;
                acc[r][1] += xv.x*w1.x + xv.y*w1.y + xv.z*w1.z + xv.w*w1.w;
                acc[r][2] += xv.x*w2.x + xv.y*w2.y + xv.z*w2.z + xv.w*w2.w;
                acc[r][3] += xv.x*w3.x + xv.y*w3.y + xv.z*w3.z + xv.w*w3.w;
            }
        }
        __syncthreads();
    }
    #pragma unroll
    for (int r = 0; r < 8; r++) {
        #pragma unroll
        for (int j = 0; j < 4; j++) {
            float v = acc[r][j];
            #pragma unroll
            for (int o = 16; o; o >>= 1) v += __shfl_xor_sync(0xffffffffu, v, o);
            if (lane == 0) {
                float y = v + bias[n0 + j];
                C[(size_t)r * ldc + n0 + j] = relu ? fmaxf(y, 0.f) : y;
            }
        }
    }
}

// ---------------- cross attention (256 encoder keys, key bias) ----------------
__global__ __launch_bounds__(256)
void cross_attn_k(const float* __restrict__ Q, int nq,
                  const float* __restrict__ Kp,
                  const float* __restrict__ Vp,
                  const float* __restrict__ bias,
                  float* __restrict__ Out)
{
    __shared__ float qs[8][193];
    __shared__ float ks[32][193];
    __shared__ float sc[8][256];
    const int bh = blockIdx.x;
    const int b = bh / cNH, h = bh % cNH;
    const int i0 = blockIdx.y * 8;
    const int ni = min(8, nq - i0);
    const int tid = threadIdx.x;
    const float scale = 0.07216878364870322f;

    for (int idx = tid; idx < ni * cDH; idx += 256) {
        int i = idx / cDH, d = idx % cDH;
        qs[i][d] = Q[(size_t)(b * nq + i0 + i) * cH + h * cDH + d];
    }
    __syncthreads();

    for (int jt = 0; jt < cS; jt += 32) {
        for (int idx = tid; idx < 32 * cDH; idx += 256) {
            int j = idx / cDH, d = idx % cDH;
            ks[j][d] = Kp[(size_t)(b * cS + jt + j) * cH + h * cDH + d];
        }
        __syncthreads();
        {
            int i = tid >> 5, j = tid & 31;
            if (i < ni) {
                float s = 0.f;
                #pragma unroll 8
                for (int d = 0; d < cDH; d++) s += qs[i][d] * ks[j][d];
                sc[i][jt + j] = s * scale + bias[b * cS + jt + j];
            }
        }
        __syncthreads();
    }

    {
        int w = tid >> 5, lane = tid & 31;
        if (w < ni) {
            float mx = -3.4e38f;
            for (int j = lane; j < cS; j += 32) mx = fmaxf(mx, sc[w][j]);
            #pragma unroll
            for (int o = 16; o; o >>= 1) mx = fmaxf(mx, __shfl_xor_sync(0xffffffffu, mx, o));
            float sum = 0.f;
            for (int j = lane; j < cS; j += 32) {
                float e = expf(sc[w][j] - mx);
                sc[w][j] = e; sum += e;
            }
            #pragma unroll
            for (int o = 16; o; o >>= 1) sum += __shfl_xor_sync(0xffffffffu, sum, o);
            float inv = 1.f / sum;
            for (int j = lane; j < cS; j += 32) sc[w][j] *= inv;
        }
    }
    __syncthreads();

    {
        int i = tid >> 5, lane = tid & 31;
        float oacc[6] = {0.f, 0.f, 0.f, 0.f, 0.f, 0.f};
        for (int jt = 0; jt < cS; jt += 32) {
            for (int idx = tid; idx < 32 * cDH; idx += 256) {
                int j = idx / cDH, d = idx % cDH;
                ks[j][d] = Vp[(size_t)(b * cS + jt + j) * cH + h * cDH + d];
            }
            __syncthreads();
            if (i < ni) {
                float p = sc[i][jt + lane];
                #pragma unroll 8
                for (int j = 0; j < 32; j++) {
                    float pj = __shfl_sync(0xffffffffu, p, j);
                    #pragma unroll
                    for (int k = 0; k < 6; k++)
                        oacc[k] += pj * ks[j][lane + 32 * k];
                }
            }
            __syncthreads();
        }
        if (i < ni) {
            #pragma unroll
            for (int k = 0; k < 6; k++)
                Out[(size_t)(b * nq + i0 + i) * cH + h * cDH + lane + 32 * k] = oacc[k];
        }
    }
}

// ---------------- self attention over decoder tokens (L<=32) ----------------
__global__ __launch_bounds__(256)
void self_attn_k(const float* __restrict__ QKV, int rs, int L,
                 float* __restrict__ Out, int lastonly)
{
    __shared__ float ks[32][193];
    __shared__ float sc[32][33];
    const int b = blockIdx.x / cNH, h = blockIdx.x % cNH;
    const int tid = threadIdx.x;
    const float scale = 0.07216878364870322f;

    for (int idx = tid; idx < L * cDH; idx += 256) {
        int j = idx / cDH, d = idx % cDH;
        ks[j][d] = QKV[(size_t)(b * rs + j) * (3 * cH) + cH + h * cDH + d];
    }
    __syncthreads();

    const int i_lo = lastonly ? (L - 1) : 0;
    const int nq2 = lastonly ? 1 : L;
    for (int idx = tid; idx < nq2 * L; idx += 256) {
        int r = idx / L, j = idx % L;
        const float* q = QKV + (size_t)(b * rs + i_lo + r) * (3 * cH) + h * cDH;
        float s = 0.f;
        #pragma unroll 8
        for (int d = 0; d < cDH; d++) s += q[d] * ks[j][d];
        sc[r][j] = s * scale;
    }
    __syncthreads();

    {
        int w = tid >> 5, lane = tid & 31;
        for (int r = w; r < nq2; r += 8) {
            float x = (lane < L) ? sc[r][lane] : -3.4e38f;
            float mx = x;
            #pragma unroll
            for (int o = 16; o; o >>= 1) mx = fmaxf(mx, __shfl_xor_sync(0xffffffffu, mx, o));
            float e = (lane < L) ? expf(x - mx) : 0.f;
            float sum = e;
            #pragma unroll
            for (int o = 16; o; o >>= 1) sum += __shfl_xor_sync(0xffffffffu, sum, o);
            if (lane < L) sc[r][lane] = e / sum;
        }
    }
    __syncthreads();

    for (int idx = tid; idx < L * cDH; idx += 256) {
        int j = idx / cDH, d = idx % cDH;
        ks[j][d] = QKV[(size_t)(b * rs + j) * (3 * cH) + 2 * cH + h * cDH + d];
    }
    __syncthreads();

    if (lastonly) {
        if (tid < cDH) {
            float acc = 0.f;
            for (int j = 0; j < L; j++) acc += sc[0][j] * ks[j][tid];
            Out[(size_t)b * cH + h * cDH + tid] = acc;
        }
    } else {
        int w = tid >> 5, lane = tid & 31;
        for (int r = w; r < L; r += 8) {
            #pragma unroll
            for (int k = 0; k < 6; k++) {
                int d = lane + 32 * k;
                float acc = 0.f;
                for (int j = 0; j < L; j++) acc += sc[r][j] * ks[j][d];
                Out[(size_t)(b * L + r) * cH + h * cDH + d] = acc;
            }
        }
    }
}

// ---------------- fused residual + LayerNorm ----------------
__global__ __launch_bounds__(256)
void add_ln_k(const float* __restrict__ X, int sx,
              const float* __restrict__ Hh, int sh,
              float* __restrict__ Y, int sy, int Lq,
              const float* __restrict__ gamma,
              const float* __restrict__ beta)
{
    const int m = blockIdx.x;
    const int bb = m / Lq, l = m - bb * Lq;
    const float* x = X + ((size_t)bb * sx + l) * cH;
    const float* hh = Hh + ((size_t)bb * sh + l) * cH;
    float* y = Y + ((size_t)bb * sy + l) * cH;
    const int tid = threadIdx.x;
    __shared__ float red[8];

    float v0 = x[tid] + hh[tid];
    float v1 = x[tid + 256] + hh[tid + 256];
    float v2 = x[tid + 512] + hh[tid + 512];
    float s = v0 + v1 + v2;
    #pragma unroll
    for (int o = 16; o; o >>= 1) s += __shfl_xor_sync(0xffffffffu, s, o);
    if ((tid & 31) == 0) red[tid >> 5] = s;
    __syncthreads();
    float tot = 0.f;
    #pragma unroll
    for (int k = 0; k < 8; k++) tot += red[k];
    float mean = tot * (1.f / 768.f);
    float d0 = v0 - mean, d1 = v1 - mean, d2 = v2 - mean;
    float q = d0 * d0 + d1 * d1 + d2 * d2;
    #pragma unroll
    for (int o = 16; o; o >>= 1) q += __shfl_xor_sync(0xffffffffu, q, o);
    __syncthreads();
    if ((tid & 31) == 0) red[tid >> 5] = q;
    __syncthreads();
    float vq = 0.f;
    #pragma unroll
    for (int k = 0; k < 8; k++) vq += red[k];
    float inv = rsqrtf(vq * (1.f / 768.f) + 1e-5f);
    y[tid]       = d0 * inv * gamma[tid]       + beta[tid];
    y[tid + 256] = d1 * inv * gamma[tid + 256] + beta[tid + 256];
    y[tid + 512] = d2 * inv * gamma[tid + 512] + beta[tid + 512];
}

// ---------------- misc ----------------
__global__ void bias_k(const int* __restrict__ mask, float* __restrict__ out)
{
    int i = blockIdx.x * 256 + threadIdx.x;
    if (i < cB * cS) out[i] = (mask[i] == 0) ? -1e9f : 0.f;
}

__global__ void embed0_k(const int* __restrict__ sent, const float* __restrict__ temb,
                         float* __restrict__ dec)
{
    int b = blockIdx.x;
    int s = sent[b];
    for (int d = threadIdx.x; d < cH; d += 256)
        dec[b * cH + d] = temb[s * cH + d];
}

__global__ __launch_bounds__(256)
void argmax_embed_k(const float* __restrict__ logits, int ldl,
                    const float* __restrict__ tok_w,
                    const float* __restrict__ tok_b,
                    float* __restrict__ dec)
{
    const int b = blockIdx.x;
    const float* row = logits + (size_t)b * ldl;
    const int tid = threadIdx.x;
    float best = -3.4e38f;
    int bidx = 0x7fffffff;
    for (int v = tid; v < cV; v += 256) {
        float x = row[v];
        if (x > best || (x == best && v < bidx)) { best = x; bidx = v; }
    }
    __shared__ float sv[256];
    __shared__ int si[256];
    sv[tid] = best; si[tid] = bidx;
    __syncthreads();
    for (int s = 128; s; s >>= 1) {
        if (tid < s) {
            if (sv[tid + s] > sv[tid] || (sv[tid + s] == sv[tid] && si[tid + s] < si[tid])) {
                sv[tid] = sv[tid + s]; si[tid] = si[tid + s];
            }
        }
        __syncthreads();
    }
    int id = si[0];
    for (int d = tid; d < cH; d += 256)
        dec[b * cH + d] = tok_w[(size_t)d * cV + id] + tok_b[d];
}

// ---------------- host ----------------
extern "C" void kernel_launch(void* const* d_in, const int* in_sizes, int n_in,
                              void* d_out, int out_size)
{
    (void)in_sizes; (void)n_in; (void)out_size;
    const float* hs          = (const float*)d_in[0];
    const int*   sent        = (const int*)d_in[1];
    const int*   amask       = (const int*)d_in[2];
    const float* temb        = (const float*)d_in[5];
    const float* ctx_in_w    = (const float*)d_in[6];
    const float* ctx_in_b    = (const float*)d_in[7];
    const float* ctx_out_w   = (const float*)d_in[8];
    const float* ctx_out_b   = (const float*)d_in[9];
    const float* self_in_w   = (const float*)d_in[10];
    const float* self_in_b   = (const float*)d_in[11];
    const float* self_out_w  = (const float*)d_in[12];
    const float* self_out_b  = (const float*)d_in[13];
    const float* cross_in_w  = (const float*)d_in[14];
    const float* cross_in_b  = (const float*)d_in[15];
    const float* cross_out_w = (const float*)d_in[16];
    const float* cross_out_b = (const float*)d_in[17];
    const float* ff1_w       = (const float*)d_in[18];
    const float* ff1_b       = (const float*)d_in[19];
    const float* ff2_w       = (const float*)d_in[20];
    const float* ff2_b       = (const float*)d_in[21];
    const float* norm_g      = (const float*)d_in[22];
    const float* norm_b      = (const float*)d_in[23];
    const float* out_w       = (const float*)d_in[24];
    const float* out_b       = (const float*)d_in[25];
    const float* tok_w       = (const float*)d_in[26];
    const float* tok_b       = (const float*)d_in[27];
    float* out = (float*)d_out;

    float *pBias, *pK, *pV, *pXctx, *pQkv0, *pDec, *pQnew, *pRaw1, *pH8, *pX8, *pFF8;
    float *pX1, *pHb, *pQkv1, *pQb, *pRawb, *pFFb, *pPart;
    int *pCnt;
    cudaGetSymbolAddress((void**)&pBias, g_bias);
    cudaGetSymbolAddress((void**)&pK,    g_Kc);
    cudaGetSymbolAddress((void**)&pV,    g_Vc);
    cudaGetSymbolAddress((void**)&pXctx, g_xctx);
    cudaGetSymbolAddress((void**)&pQkv0, g_qkv0);
    cudaGetSymbolAddress((void**)&pDec,  g_dec);
    cudaGetSymbolAddress((void**)&pQnew, g_qnew);
    cudaGetSymbolAddress((void**)&pRaw1, g_raw1);
    cudaGetSymbolAddress((void**)&pH8,   g_h8);
    cudaGetSymbolAddress((void**)&pX8,   g_x8);
    cudaGetSymbolAddress((void**)&pFF8,  g_ff8);
    cudaGetSymbolAddress((void**)&pX1,   g_x1);
    cudaGetSymbolAddress((void**)&pHb,   g_hb);
    cudaGetSymbolAddress((void**)&pQkv1, g_qkv1);
    cudaGetSymbolAddress((void**)&pQb,   g_qb);
    cudaGetSymbolAddress((void**)&pRawb, g_rawb);
    cudaGetSymbolAddress((void**)&pFFb,  g_ffb);
    cudaGetSymbolAddress((void**)&pPart, g_part);
    cudaGetSymbolAddress((void**)&pCnt,  g_cnt);

    auto gemv = [](const float* X, int lda, const float* W, const float* bias,
                   float* C, int ldc, int N, int K, int relu) {
        gemv_w4<<<N / 32, 256>>>(X, lda, W, bias, C, ldc, N, K, relu);
    };

    // batch GEMM with fused split-K (single launch, deterministic)
    auto gemm = [&](const float* A, int lda, const float* W, const float* bias,
                    float* C, int ldc, int M, int N, int K, int relu) {
        if (M == 8) { gemv_w4<<<N / 32, 256>>>(A, lda, W, bias, C, ldc, N, K, relu); return; }
        int gx = N / 128, gy = (M + 63) / 64;
        int g = gx * gy;
        int S = 1;
        while (S < 16 && g * S < 296 && (size_t)(S << 1) * M * N <= (size_t)PARTCAP
               && (K / (S << 1)) % 16 == 0) S <<= 1;
        gemm_sk<<<dim3(gx, gy, S), 256>>>(A, lda, W, bias, C, ldc, pPart, pCnt, M, N, K, relu);
    };

    // ---- precompute ----
    bias_k<<<8, 256>>>(amask, pBias);
    for (int m = 0; m < 3; m++) {
        const float* w = (m == 0) ? ctx_in_w : cross_in_w + (size_t)(m - 1) * 3 * cH * cH;
        const float* bb = (m == 0) ? ctx_in_b : cross_in_b + (size_t)(m - 1) * 3 * cH;
        gemm(hs, cH, w + (size_t)cH * cH,     bb + cH,     pK + (size_t)m * BSH, cH, cB * cS, cH, cH, 0);
        gemm(hs, cH, w + (size_t)2 * cH * cH, bb + 2 * cH, pV + (size_t)m * BSH, cH, cB * cS, cH, cH, 0);
    }

    // ---- generation loop ----
    for (int t = 0; t < cSTEPS; t++) {
        const int L = t + 1;
        const int M = cB * L;

        if (t == 0) embed0_k<<<8, 256>>>(sent, temb, pDec);
        else        argmax_embed_k<<<8, 256>>>(out + (size_t)(t - 1) * cV, cSTEPS * cV,
                                               tok_w, tok_b, pDec);

        // ctx attention for the new token -> cache slot t
        gemv(pDec, cH, ctx_in_w, ctx_in_b, pQnew, cH, cH, cH, 0);
        cross_attn_k<<<dim3(cB * cNH, 1), 256>>>(pQnew, 1, pK, pV, pBias, pRaw1);
        gemv(pRaw1, cH, ctx_out_w, ctx_out_b, pXctx + (size_t)t * cH, cSTEPS * cH, cH, cH, 0);
        gemv(pXctx + (size_t)t * cH, cSTEPS * cH, self_in_w, self_in_b,
             pQkv0 + (size_t)t * 3 * cH, cSTEPS * 3 * cH, 3 * cH, cH, 0);

        // ---- layer 0 (all L positions) ----
        self_attn_k<<<cB * cNH, 256>>>(pQkv0, cSTEPS, L, pRawb, 0);
        gemm(pRawb, cH, self_out_w, self_out_b, pHb, cH, M, cH, cH, 0);
        add_ln_k<<<M, 256>>>(pXctx, cSTEPS, pHb, L, pX1, L, L,
                             norm_g + 0 * cH, norm_b + 0 * cH);
        gemm(pX1, cH, cross_in_w, cross_in_b, pQb, cH, M, cH, cH, 0);
        cross_attn_k<<<dim3(cB * cNH, (L + 7) / 8), 256>>>(pQb, L, pK + BSH, pV + BSH, pBias, pRawb);
        gemm(pRawb, cH, cross_out_w, cross_out_b, pHb, cH, M, cH, cH, 0);
        add_ln_k<<<M, 256>>>(pX1, L, pHb, L, pX1, L, L,
                             norm_g + 1 * cH, norm_b + 1 * cH);
        gemm(pX1, cH, ff1_w, ff1_b, pFFb, cFF, M, cFF, cH, 1);
        gemm(pFFb, cFF, ff2_w, ff2_b, pHb, cH, M, cH, cFF, 0);
        add_ln_k<<<M, 256>>>(pX1, L, pHb, L, pX1, L, L,
                             norm_g + 2 * cH, norm_b + 2 * cH);

        // ---- layer 1 (QKV for all L, rest last-position-only) ----
        gemm(pX1, cH, self_in_w + (size_t)3 * cH * cH, self_in_b + 3 * cH,
             pQkv1, 3 * cH, M, 3 * cH, cH, 0);
        self_attn_k<<<cB * cNH, 256>>>(pQkv1, L, L, pRaw1, 1);
        gemv(pRaw1, cH, self_out_w + (size_t)cH * cH, self_out_b + cH, pH8, cH, cH, cH, 0);
        add_ln_k<<<cB, 256>>>(pX1 + (size_t)(L - 1) * cH, L, pH8, 1, pX8, 1, 1,
                              norm_g + 3 * cH, norm_b + 3 * cH);
        gemv(pX8, cH, cross_in_w + (size_t)3 * cH * cH, cross_in_b + 3 * cH, pQnew, cH, cH, cH, 0);
        cross_attn_k<<<dim3(cB * cNH, 1), 256>>>(pQnew, 1, pK + 2 * BSH, pV + 2 * BSH, pBias, pRaw1);
        gemv(pRaw1, cH, cross_out_w + (size_t)cH * cH, cross_out_b + cH, pH8, cH, cH, cH, 0);
        add_ln_k<<<cB, 256>>>(pX8, 1, pH8, 1, pX8, 1, 1,
                              norm_g + 4 * cH, norm_b + 4 * cH);
        gemv(pX8, cH, ff1_w + (size_t)cFF * cH, ff1_b + cFF, pFF8, cFF, cFF, cH, 1);
        gemv(pFF8, cFF, ff2_w + (size_t)cH * cFF, ff2_b + cH, pH8, cH, cH, cFF, 0);
        add_ln_k<<<cB, 256>>>(pX8, 1, pH8, 1, pX8, 1, 1,
                              norm_g + 5 * cH, norm_b + 5 * cH);

        // ---- logits for this step ----
        gemv(pX8, cH, out_w, out_b, out + (size_t)t * cV, cSTEPS * cV, cV, cH, 0);
    }
}